// round 1
// baseline (speedup 1.0000x reference)
#include <cuda_runtime.h>
#include <cuda_bf16.h>
#include <math.h>

// Problem constants
#define NTOT 32768      // 32*32*32 flattened vectors
#define DIM  128
#define KC   4096       // num embeddings
#define BATCH 32
#define HW   32
#define CHW  131072     // 128*32*32 elements per batch image

// Output layout (concatenated, float32):
// [0, 4194304)                quantized_st (NCHW)
// [4194304]                   loss
// [4194305]                   perplexity
// [4194306, 4194306+134217728) encodings one-hot [N,K]
// [138412034, 138444802)      encoding_indices (as float)
#define OFF_LOSS 4194304
#define OFF_PERP 4194305
#define OFF_ENC  4194306
#define OFF_IDX  138412034

// ---------------- device scratch (no allocation allowed) ----------------
__device__ float g_Wt[DIM * KC];     // transposed weight [d][k]  (2 MB)
__device__ float g_wsq[KC];
__device__ int   g_idx[NTOT];
__device__ int   g_counts[KC];
__device__ float g_partials[1024];

// ---------------- packed f32x2 helpers ----------------
__device__ __forceinline__ unsigned long long pack2(float x, float y) {
    unsigned long long r;
    asm("mov.b64 %0, {%1, %2};" : "=l"(r) : "f"(x), "f"(y));
    return r;
}
__device__ __forceinline__ void unpack2(unsigned long long v, float& x, float& y) {
    asm("mov.b64 {%0, %1}, %2;" : "=f"(x), "=f"(y) : "l"(v));
}
__device__ __forceinline__ void fma2(unsigned long long& d, unsigned long long a, unsigned long long b) {
    asm("fma.rn.f32x2 %0, %1, %2, %0;" : "+l"(d) : "l"(a), "l"(b));
}

// ---------------- prep kernels ----------------
__global__ void transpose_w_kernel(const float* __restrict__ w) {
    __shared__ float t[32][33];
    int k0 = blockIdx.x * 32, d0 = blockIdx.y * 32;
    t[threadIdx.y][threadIdx.x] = w[(k0 + threadIdx.y) * DIM + d0 + threadIdx.x];
    __syncthreads();
    g_Wt[(size_t)(d0 + threadIdx.y) * KC + k0 + threadIdx.x] = t[threadIdx.x][threadIdx.y];
}

__global__ void wsq_kernel(const float* __restrict__ w) {
    int warp = threadIdx.x >> 5, lane = threadIdx.x & 31;
    int k = blockIdx.x * 8 + warp;
    float4 v = ((const float4*)w)[k * 32 + lane];
    float s = v.x * v.x + v.y * v.y + v.z * v.z + v.w * v.w;
    #pragma unroll
    for (int o = 16; o; o >>= 1) s += __shfl_down_sync(0xffffffffu, s, o);
    if (lane == 0) g_wsq[k] = s;
}

__global__ void zero_counts_kernel() {
    g_counts[blockIdx.x * 256 + threadIdx.x] = 0;
}

// ---------------- fused distance GEMM + argmin ----------------
// Block: 128 rows (n) x all 4096 codes, tiled BN=128. 256 threads, 8x8 micro-tile.
// smem: xs[kk][r] (k-major x tile), ws[kk][c] (k-major weight tile from g_Wt).
__global__ void __launch_bounds__(256, 1) argmin_kernel(const float* __restrict__ x) {
    extern __shared__ float sm[];
    float* xs = sm;            // 128*128
    float* ws = sm + 16384;    // 128*128
    __shared__ float xsq_s[128];
    __shared__ float wsq_s[128];
    __shared__ float rv[128][16];
    __shared__ int   ri[128][16];

    const int tid = threadIdx.x;
    const int n0 = blockIdx.x << 7;
    const int b  = n0 >> 10;          // batch index
    const int nb = n0 & 1023;         // offset within batch's 1024 (h,w) positions

    float4* xs4 = (float4*)xs;
    float4* ws4 = (float4*)ws;
    const float4* xg = (const float4*)(x + (size_t)b * CHW + nb);
    // xs[kk][r] = x[b, kk, nb+r]; contiguous in r -> coalesced copy
    #pragma unroll
    for (int i = tid; i < 4096; i += 256) {
        int kk = i >> 5, r4 = i & 31;
        xs4[i] = xg[kk * 256 + r4];
    }
    __syncthreads();

    if (tid < 128) {
        float s = 0.f;
        #pragma unroll 8
        for (int kk = 0; kk < 128; kk++) { float v = xs[kk * 128 + tid]; s = fmaf(v, v, s); }
        xsq_s[tid] = s + 1e-8f;
    }

    const int tr = tid >> 4;   // 0..15 row group
    const int tc = tid & 15;   // 0..15 col group
    float bval[8]; int bidx[8];
    #pragma unroll
    for (int m = 0; m < 8; m++) { bval[m] = 3.4e38f; bidx[m] = 0; }

    const float4* wt4 = (const float4*)g_Wt;
    const float4* xa = xs4 + tr * 2;
    const float4* wb = ws4 + tc * 2;

    for (int t = 0; t < 32; t++) {
        const int k0 = t << 7;
        __syncthreads();   // previous epilogue done with ws/wsq_s; also orders xsq_s at t=0
        #pragma unroll
        for (int i = tid; i < 4096; i += 256) {
            int kk = i >> 5, c4 = i & 31;
            ws4[i] = wt4[kk * 1024 + (k0 >> 2) + c4];   // Wt[kk][k0..k0+127]
        }
        if (tid < 128) wsq_s[tid] = g_wsq[k0 + tid];
        __syncthreads();

        unsigned long long acc[8][4];
        #pragma unroll
        for (int m = 0; m < 8; m++)
            #pragma unroll
            for (int p = 0; p < 4; p++) acc[m][p] = 0ull;   // (0.f, 0.f)

        #pragma unroll 8
        for (int kk = 0; kk < 128; kk++) {
            float4 a0 = xa[kk * 32];
            float4 a1 = xa[kk * 32 + 1];
            float4 b0 = wb[kk * 32];
            float4 b1 = wb[kk * 32 + 1];
            unsigned long long bp[4];
            bp[0] = pack2(b0.x, b0.y); bp[1] = pack2(b0.z, b0.w);
            bp[2] = pack2(b1.x, b1.y); bp[3] = pack2(b1.z, b1.w);
            float av[8] = {a0.x, a0.y, a0.z, a0.w, a1.x, a1.y, a1.z, a1.w};
            #pragma unroll
            for (int m = 0; m < 8; m++) {
                unsigned long long am = pack2(av[m], av[m]);
                #pragma unroll
                for (int p = 0; p < 4; p++) fma2(acc[m][p], am, bp[p]);
            }
        }

        // epilogue: dist = xsq - 2*dot + wsq (+1e-8 folded into xsq_s)
        #pragma unroll
        for (int m = 0; m < 8; m++) {
            float xq = xsq_s[tr * 8 + m];
            #pragma unroll
            for (int p = 0; p < 4; p++) {
                float d0, d1;
                unpack2(acc[m][p], d0, d1);
                int c = tc * 8 + p * 2;
                float dist0 = xq - 2.f * d0 + wsq_s[c];
                float dist1 = xq - 2.f * d1 + wsq_s[c + 1];
                if (dist0 < bval[m]) { bval[m] = dist0; bidx[m] = k0 + c; }
                if (dist1 < bval[m]) { bval[m] = dist1; bidx[m] = k0 + c + 1; }
            }
        }
    }

    #pragma unroll
    for (int m = 0; m < 8; m++) { rv[tr * 8 + m][tc] = bval[m]; ri[tr * 8 + m][tc] = bidx[m]; }
    __syncthreads();
    if (tid < 128) {
        float bv = rv[tid][0]; int bi = ri[tid][0];
        #pragma unroll
        for (int j = 1; j < 16; j++) {
            float v = rv[tid][j]; int ii = ri[tid][j];
            if (v < bv || (v == bv && ii < bi)) { bv = v; bi = ii; }
        }
        g_idx[n0 + tid] = bi;
    }
}

// ---------------- gather quantized + loss partials ----------------
// Each block: one (b,h) pair => 32 n's (w=0..31) x 128 d. Writes NCHW coalesced along w.
__global__ void gather_kernel(const float* __restrict__ x, const float* __restrict__ wgt,
                              float* __restrict__ outq) {
    __shared__ int idx_s[32];
    __shared__ float red[256];
    const int blk = blockIdx.x;
    const int b = blk >> 5, h = blk & 31;
    const int n0 = blk * 32;
    const int tid = threadIdx.x;
    if (tid < 32) idx_s[tid] = g_idx[n0 + tid];
    __syncthreads();

    const int w = tid & 31, dg = tid >> 5;   // warp = fixed dg, w 0..31 (coalesced I/O)
    const size_t base = (size_t)b * CHW + h * 32 + w;
    float sum = 0.f;
    #pragma unroll
    for (int j = 0; j < 16; j++) {
        int d = dg + (j << 3);
        size_t lin = base + (size_t)d * 1024;
        float q = wgt[idx_s[w] * DIM + d];   // L2-resident gather
        float xv = x[lin];
        outq[lin] = q;
        float df = q - xv;
        sum = fmaf(df, df, sum);
    }
    red[tid] = sum;
    __syncthreads();
    #pragma unroll
    for (int o = 128; o; o >>= 1) { if (tid < o) red[tid] += red[tid + o]; __syncthreads(); }
    if (tid == 0) g_partials[blk] = red[0];
}

// ---------------- counts + float indices ----------------
__global__ void counts_kernel(float* __restrict__ out_idx) {
    int n = blockIdx.x * 256 + threadIdx.x;
    int id = g_idx[n];
    atomicAdd(&g_counts[id], 1);
    out_idx[n] = (float)id;
}

// ---------------- encodings scatter (region pre-zeroed by memset) ----------------
__global__ void scatter_kernel(float* __restrict__ enc) {
    int n = blockIdx.x * 256 + threadIdx.x;
    enc[(size_t)n * KC + g_idx[n]] = 1.0f;
}

// ---------------- finalize: loss + perplexity ----------------
__global__ void finalize_kernel(float* __restrict__ out_loss, float* __restrict__ out_perp) {
    __shared__ float red[256];
    const int tid = threadIdx.x;

    float s = 0.f;
    for (int i = tid; i < 1024; i += 256) s += g_partials[i];
    red[tid] = s;
    __syncthreads();
    #pragma unroll
    for (int o = 128; o; o >>= 1) { if (tid < o) red[tid] += red[tid + o]; __syncthreads(); }
    if (tid == 0) {
        float mse = red[0] * (1.0f / 4194304.0f);
        float loss = mse * (1.0f + 0.25f);   // q_latent + commitment * e_latent (equal values)
        if (isnan(loss) || isinf(loss)) loss = 0.1f;
        *out_loss = loss;
    }
    __syncthreads();

    float hsum = 0.f;
    for (int i = tid; i < KC; i += 256) {
        float p = (float)g_counts[i] * (1.0f / (float)NTOT);
        hsum += p * logf(p + 1e-10f);
    }
    red[tid] = hsum;
    __syncthreads();
    #pragma unroll
    for (int o = 128; o; o >>= 1) { if (tid < o) red[tid] += red[tid + o]; __syncthreads(); }
    if (tid == 0) *out_perp = expf(-red[0]);
}

// ---------------- launch ----------------
extern "C" void kernel_launch(void* const* d_in, const int* in_sizes, int n_in,
                              void* d_out, int out_size) {
    const float* x;
    const float* w;
    if (in_sizes[0] == NTOT * DIM * 4 / 4 * 1 && in_sizes[0] == 4194304) { // inputs first
        x = (const float*)d_in[0]; w = (const float*)d_in[1];
    } else if (in_sizes[0] == KC * DIM) {                                  // weight first
        w = (const float*)d_in[0]; x = (const float*)d_in[1];
    } else {
        x = (const float*)d_in[0]; w = (const float*)d_in[1];
    }

    float* out = (float*)d_out;
    float* out_q    = out;
    float* out_loss = out + OFF_LOSS;
    float* out_perp = out + OFF_PERP;
    float* out_enc  = out + OFF_ENC;
    float* out_idx  = out + OFF_IDX;

    cudaFuncSetAttribute(argmin_kernel, cudaFuncAttributeMaxDynamicSharedMemorySize, 131072);

    transpose_w_kernel<<<dim3(128, 4), dim3(32, 32)>>>(w);
    wsq_kernel<<<512, 256>>>(w);
    zero_counts_kernel<<<16, 256>>>();
    argmin_kernel<<<256, 256, 131072>>>(x);
    gather_kernel<<<1024, 256>>>(x, w, out_q);
    counts_kernel<<<128, 256>>>(out_idx);
    cudaMemsetAsync(out_enc, 0, (size_t)134217728 * sizeof(float));
    scatter_kernel<<<128, 256>>>(out_enc);
    finalize_kernel<<<1, 256>>>(out_loss, out_perp);
}

// round 4
// speedup vs baseline: 1.1188x; 1.1188x over previous
#include <cuda_runtime.h>
#include <cuda_fp16.h>
#include <math.h>
#include <stdint.h>

#define NTOT 32768
#define DIM  128
#define KC   4096
#define CHW  131072

#define OFF_LOSS 4194304
#define OFF_PERP 4194305
#define OFF_ENC  4194306
#define OFF_IDX  138412034

#define GAP_THRESH 3e-4f

// ---------------- device scratch ----------------
__device__ __align__(16) __half g_Bp[KC * 384];   // [code][ w_hi(128) | w_lo(128) | w_hi(128) ], w scaled x64 (3MB)
__device__ float g_wsq[KC];
__device__ int   g_idx[NTOT];
__device__ int   g_counts[KC];
__device__ float g_partials[1024];
__device__ int   g_flag[NTOT];
__device__ int   g_nflag;

// ---------------- PTX helpers ----------------
__device__ __forceinline__ uint32_t smem_u32(const void* p) {
    uint32_t a;
    asm("{ .reg .u64 t; cvta.to.shared.u64 t, %1; cvt.u32.u64 %0, t; }" : "=r"(a) : "l"(p));
    return a;
}
__device__ __forceinline__ void cp_async16(uint32_t dst, const void* src) {
    asm volatile("cp.async.cg.shared.global [%0], [%1], 16;" :: "r"(dst), "l"(src) : "memory");
}
#define CP_COMMIT() asm volatile("cp.async.commit_group;" ::: "memory")
#define CP_WAIT2()  asm volatile("cp.async.wait_group 2;" ::: "memory")

#define LDSM4(R, addr) \
    asm volatile("ldmatrix.sync.aligned.m8n8.x4.shared.b16 {%0,%1,%2,%3}, [%4];" \
        : "=r"((R)[0]), "=r"((R)[1]), "=r"((R)[2]), "=r"((R)[3]) : "r"(addr))

#define MMA16816(C, A, b0, b1) \
    asm volatile("mma.sync.aligned.m16n8k16.row.col.f32.f16.f16.f32 " \
        "{%0,%1,%2,%3}, {%4,%5,%6,%7}, {%8,%9}, {%0,%1,%2,%3};" \
        : "+f"((C)[0]), "+f"((C)[1]), "+f"((C)[2]), "+f"((C)[3]) \
        : "r"((A)[0]), "r"((A)[1]), "r"((A)[2]), "r"((A)[3]), "r"(b0), "r"(b1))

// ---------------- prep: split scaled W into fp16 hi/lo triplet rows ----------------
__global__ void prep_w_kernel(const float* __restrict__ w) {
    int i = blockIdx.x * 256 + threadIdx.x;     // 0..524287
    int k = i >> 7, d = i & 127;
    float v = w[i] * 64.0f;
    __half h = __float2half_rn(v);
    __half l = __float2half_rn(v - __half2float(h));
    g_Bp[k * 384 + d]       = h;
    g_Bp[k * 384 + 128 + d] = l;
    g_Bp[k * 384 + 256 + d] = h;
}

__global__ void wsq_kernel(const float* __restrict__ w) {
    int warp = threadIdx.x >> 5, lane = threadIdx.x & 31;
    int k = blockIdx.x * 8 + warp;
    float4 v = ((const float4*)w)[k * 32 + lane];
    float s = v.x * v.x + v.y * v.y + v.z * v.z + v.w * v.w;
    #pragma unroll
    for (int o = 16; o; o >>= 1) s += __shfl_down_sync(0xffffffffu, s, o);
    if (lane == 0) g_wsq[k] = s;
}

__global__ void zero_counts_kernel() {
    g_counts[blockIdx.x * 256 + threadIdx.x] = 0;
    if (blockIdx.x == 0 && threadIdx.x == 0) g_nflag = 0;
}

// ---------------- fp16 split-precision mma.sync distance GEMM + fused top-2 argmin ----------------
#define A_PITCH 392
#define B_STG   18432
#define SM_A    0
#define SM_B    100352
#define SM_WSQ  174080
#define SM_XSQ  190464
#define SM_RV   190976
#define SM_RI   193024
#define SM_R2   195072
#define SMEM_TOTAL 197120

__global__ void __launch_bounds__(256, 1) argmin_mma_kernel(const float* __restrict__ x) {
    extern __shared__ char sm[];
    __half* Asm   = (__half*)(sm + SM_A);
    float*  wsq_s = (float*)(sm + SM_WSQ);
    float*  xsq_s = (float*)(sm + SM_XSQ);
    float*  rv    = (float*)(sm + SM_RV);
    int*    ri    = (int*)(sm + SM_RI);
    float*  r2    = (float*)(sm + SM_R2);
    const uint32_t smb = smem_u32(sm);

    const int tid   = threadIdx.x;
    const int lane  = tid & 31;
    const int warp  = tid >> 5;
    const int warpM = warp >> 2;      // 0..1
    const int warpN = warp & 3;       // 0..3
    const int n0 = blockIdx.x << 7;
    const int b  = n0 >> 10;
    const int nb = n0 & 1023;

    if (tid < 128) xsq_s[tid] = 0.f;
    __syncthreads();

    {
        float4* d4 = (float4*)wsq_s;
        const float4* s4 = (const float4*)g_wsq;
        #pragma unroll
        for (int i = tid; i < 1024; i += 256) d4[i] = s4[i];
    }

    // build A: [x_hi | x_hi | x_lo], accumulate row sums of x^2
    const float* xb = x + (size_t)b * CHW + nb;
    for (int it = 0; it < 64; it++) {
        int e = it * 256 + tid;
        int d = e >> 7, r = e & 127;
        float v = __ldg(xb + (size_t)d * 1024 + r);
        __half h = __float2half_rn(v);
        __half l = __float2half_rn(v - __half2float(h));
        Asm[r * A_PITCH + d]       = h;
        Asm[r * A_PITCH + 128 + d] = h;
        Asm[r * A_PITCH + 256 + d] = l;
        atomicAdd(&xsq_s[r], v * v);
    }
    __syncthreads();
    if (tid < 128) xsq_s[tid] += 1e-8f;
    __syncthreads();

    float xr[8];
    #pragma unroll
    for (int mt = 0; mt < 4; mt++) {
        int r0 = warpM * 64 + mt * 16 + (lane >> 2);
        xr[mt * 2]     = xsq_s[r0];
        xr[mt * 2 + 1] = xsq_s[r0 + 8];
    }

    const uint32_t a_base  = smb + SM_A +
        (uint32_t)((warpM * 64 + (lane & 15)) * 784 + ((lane >> 4) * 16));
    const uint32_t b_base0 = smb + SM_B +
        (uint32_t)((warpN * 32 + (lane & 7) + ((lane & 16) ? 8 : 0)) * 144 + ((lane & 8) ? 16 : 0));

    float acc[4][4][4];
    #pragma unroll
    for (int mt = 0; mt < 4; mt++)
        #pragma unroll
        for (int nt = 0; nt < 4; nt++)
            #pragma unroll
            for (int q = 0; q < 4; q++) acc[mt][nt][q] = 0.f;

    float bval[8]; int bidx[8]; float b2v[8];
    #pragma unroll
    for (int m = 0; m < 8; m++) { bval[m] = 3.4e38f; bidx[m] = 0; b2v[m] = 3.4e38f; }

    const int brow = tid >> 1;
    const int bhalf = tid & 1;
    auto issue = [&](int st) {
        int stg = st & 3;
        int c = st / 6, kq = st - c * 6;
        const char* src = (const char*)g_Bp + ((size_t)c * 128 + brow) * 768 + kq * 128 + bhalf * 64;
        uint32_t dst = smb + SM_B + stg * B_STG + brow * 144 + bhalf * 64;
        #pragma unroll
        for (int i = 0; i < 4; i++) cp_async16(dst + i * 16, src + i * 16);
    };

    issue(0); CP_COMMIT();
    issue(1); CP_COMMIT();
    issue(2); CP_COMMIT();

    for (int s = 0; s < 192; s++) {
        CP_WAIT2();
        __syncthreads();
        if (s + 3 < 192) issue(s + 3);
        CP_COMMIT();

        const int stg = s & 3;
        const int kq  = s % 6;
        const uint32_t abase = a_base + (uint32_t)(kq * 128);
        const uint32_t bbase = b_base0 + (uint32_t)(stg * B_STG);

        #pragma unroll
        for (int j = 0; j < 4; j++) {
            uint32_t ak = abase + j * 32;
            uint32_t bk = bbase + j * 32;
            uint32_t A0[4], A1[4], A2[4], A3[4], B0[4], B1[4];
            LDSM4(A0, ak);
            LDSM4(A1, ak + 16 * 784);
            LDSM4(A2, ak + 32 * 784);
            LDSM4(A3, ak + 48 * 784);
            LDSM4(B0, bk);
            LDSM4(B1, bk + 16 * 144);

            MMA16816(acc[0][0], A0, B0[0], B0[1]);
            MMA16816(acc[0][1], A0, B0[2], B0[3]);
            MMA16816(acc[0][2], A0, B1[0], B1[1]);
            MMA16816(acc[0][3], A0, B1[2], B1[3]);
            MMA16816(acc[1][0], A1, B0[0], B0[1]);
            MMA16816(acc[1][1], A1, B0[2], B0[3]);
            MMA16816(acc[1][2], A1, B1[0], B1[1]);
            MMA16816(acc[1][3], A1, B1[2], B1[3]);
            MMA16816(acc[2][0], A2, B0[0], B0[1]);
            MMA16816(acc[2][1], A2, B0[2], B0[3]);
            MMA16816(acc[2][2], A2, B1[0], B1[1]);
            MMA16816(acc[2][3], A2, B1[2], B1[3]);
            MMA16816(acc[3][0], A3, B0[0], B0[1]);
            MMA16816(acc[3][1], A3, B0[2], B0[3]);
            MMA16816(acc[3][2], A3, B1[0], B1[1]);
            MMA16816(acc[3][3], A3, B1[2], B1[3]);
        }

        if (kq == 5) {
            const int cb = (s / 6) * 128 + warpN * 32 + (lane & 3) * 2;
            #pragma unroll
            for (int nt = 0; nt < 4; nt++) {
                int c0 = cb + nt * 8;
                float w0 = wsq_s[c0], w1 = wsq_s[c0 + 1];
                #pragma unroll
                for (int mt = 0; mt < 4; mt++) {
                    float* a4 = acc[mt][nt];
                    float d00 = fmaf(a4[0], -0.03125f, xr[mt * 2])     + w0;
                    float d01 = fmaf(a4[1], -0.03125f, xr[mt * 2])     + w1;
                    float d10 = fmaf(a4[2], -0.03125f, xr[mt * 2 + 1]) + w0;
                    float d11 = fmaf(a4[3], -0.03125f, xr[mt * 2 + 1]) + w1;
                    int m0 = mt * 2, m1 = mt * 2 + 1;
                    if (d00 < bval[m0]) { b2v[m0] = bval[m0]; bval[m0] = d00; bidx[m0] = c0; }
                    else if (d00 < b2v[m0]) b2v[m0] = d00;
                    if (d01 < bval[m0]) { b2v[m0] = bval[m0]; bval[m0] = d01; bidx[m0] = c0 + 1; }
                    else if (d01 < b2v[m0]) b2v[m0] = d01;
                    if (d10 < bval[m1]) { b2v[m1] = bval[m1]; bval[m1] = d10; bidx[m1] = c0; }
                    else if (d10 < b2v[m1]) b2v[m1] = d10;
                    if (d11 < bval[m1]) { b2v[m1] = bval[m1]; bval[m1] = d11; bidx[m1] = c0 + 1; }
                    else if (d11 < b2v[m1]) b2v[m1] = d11;
                    a4[0] = 0.f; a4[1] = 0.f; a4[2] = 0.f; a4[3] = 0.f;
                }
            }
        }
    }

    // top-2 merge across the 4 lanes sharing each row
    #pragma unroll
    for (int m = 0; m < 8; m++) {
        #pragma unroll
        for (int off = 1; off < 4; off <<= 1) {
            float ov = __shfl_xor_sync(0xffffffffu, bval[m], off);
            int   oi = __shfl_xor_sync(0xffffffffu, bidx[m], off);
            float os = __shfl_xor_sync(0xffffffffu, b2v[m], off);
            if (ov < bval[m] || (ov == bval[m] && oi < bidx[m])) {
                b2v[m] = fminf(bval[m], os);
                bval[m] = ov; bidx[m] = oi;
            } else {
                b2v[m] = fminf(b2v[m], ov);
            }
        }
    }
    if ((lane & 3) == 0) {
        #pragma unroll
        for (int mt = 0; mt < 4; mt++) {
            int r0 = warpM * 64 + mt * 16 + (lane >> 2);
            rv[warpN * 128 + r0]     = bval[mt * 2];
            ri[warpN * 128 + r0]     = bidx[mt * 2];
            r2[warpN * 128 + r0]     = b2v[mt * 2];
            rv[warpN * 128 + r0 + 8] = bval[mt * 2 + 1];
            ri[warpN * 128 + r0 + 8] = bidx[mt * 2 + 1];
            r2[warpN * 128 + r0 + 8] = b2v[mt * 2 + 1];
        }
    }
    __syncthreads();
    if (tid < 128) {
        float bv = rv[tid]; int bi = ri[tid]; float s2 = r2[tid];
        #pragma unroll
        for (int q = 1; q < 4; q++) {
            float v = rv[q * 128 + tid]; int ii = ri[q * 128 + tid]; float os = r2[q * 128 + tid];
            if (v < bv || (v == bv && ii < bi)) { s2 = fminf(bv, os); bv = v; bi = ii; }
            else                                { s2 = fminf(s2, v); }
        }
        g_idx[n0 + tid] = bi;
        if (s2 - bv < GAP_THRESH) {
            int p = atomicAdd(&g_nflag, 1);
            g_flag[p] = n0 + tid;
        }
    }
}

// ---------------- rescue: exact fp32 re-argmin for near-tie rows ----------------
__global__ void __launch_bounds__(256, 1) rescue_kernel(const float* __restrict__ x,
                                                        const float* __restrict__ w) {
    __shared__ __align__(16) float xs[4][128];
    __shared__ float xsq_sh[4];
    __shared__ float redv[256];
    __shared__ int   redi[256];
    const int tid = threadIdx.x;
    const int nf = g_nflag;

    for (int base = blockIdx.x * 4; base < nf; base += gridDim.x * 4) {
        const int cnt = min(4, nf - base);
        __syncthreads();
        if (tid < 128) {
            for (int r = 0; r < cnt; r++) {
                int row = g_flag[base + r];
                int bb = row >> 10, nb = row & 1023;
                xs[r][tid] = x[(size_t)bb * CHW + (size_t)tid * 1024 + nb];
            }
        }
        __syncthreads();
        if (tid < 4) {
            float s = 0.f;
            if (tid < cnt)
                for (int d = 0; d < 128; d++) s = fmaf(xs[tid][d], xs[tid][d], s);
            xsq_sh[tid] = s + 1e-8f;
        }
        __syncthreads();

        float bv[4]; int bi[4];
        #pragma unroll
        for (int r = 0; r < 4; r++) { bv[r] = 3.4e38f; bi[r] = 0; }

        const float4* w4 = (const float4*)w;
        for (int g = 0; g < 4; g++) {
            const int k0 = g * 1024 + tid * 4;
            float dacc[4][4];
            #pragma unroll
            for (int r = 0; r < 4; r++)
                #pragma unroll
                for (int j = 0; j < 4; j++) dacc[r][j] = 0.f;
            #pragma unroll 4
            for (int d4 = 0; d4 < 32; d4++) {
                float4 xv[4];
                #pragma unroll
                for (int r = 0; r < 4; r++) xv[r] = ((const float4*)xs[r])[d4];
                #pragma unroll
                for (int j = 0; j < 4; j++) {
                    float4 wv = w4[(size_t)(k0 + j) * 32 + d4];
                    #pragma unroll
                    for (int r = 0; r < 4; r++) {
                        float t = dacc[r][j];
                        t = fmaf(xv[r].x, wv.x, t);
                        t = fmaf(xv[r].y, wv.y, t);
                        t = fmaf(xv[r].z, wv.z, t);
                        t = fmaf(xv[r].w, wv.w, t);
                        dacc[r][j] = t;
                    }
                }
            }
            #pragma unroll
            for (int j = 0; j < 4; j++) {
                int k = k0 + j;
                float wq = g_wsq[k];
                #pragma unroll
                for (int r = 0; r < 4; r++) {
                    float dist = fmaf(-2.f, dacc[r][j], xsq_sh[r]) + wq;
                    if (dist < bv[r]) { bv[r] = dist; bi[r] = k; }
                }
            }
        }

        for (int r = 0; r < cnt; r++) {
            redv[tid] = bv[r]; redi[tid] = bi[r];
            __syncthreads();
            for (int o = 128; o; o >>= 1) {
                if (tid < o) {
                    float v = redv[tid + o]; int ii = redi[tid + o];
                    if (v < redv[tid] || (v == redv[tid] && ii < redi[tid])) { redv[tid] = v; redi[tid] = ii; }
                }
                __syncthreads();
            }
            if (tid == 0) g_idx[g_flag[base + r]] = redi[0];
            __syncthreads();
        }
    }
}

// ---------------- gather quantized + loss partials ----------------
__global__ void gather_kernel(const float* __restrict__ x, const float* __restrict__ wgt,
                              float* __restrict__ outq) {
    __shared__ int idx_s[32];
    __shared__ float red[256];
    const int blk = blockIdx.x;
    const int b = blk >> 5, h = blk & 31;
    const int n0 = blk * 32;
    const int tid = threadIdx.x;
    if (tid < 32) idx_s[tid] = g_idx[n0 + tid];
    __syncthreads();

    const int w = tid & 31, dg = tid >> 5;
    const size_t bse = (size_t)b * CHW + h * 32 + w;
    float sum = 0.f;
    #pragma unroll
    for (int j = 0; j < 16; j++) {
        int d = dg + (j << 3);
        size_t lin = bse + (size_t)d * 1024;
        float q = wgt[idx_s[w] * DIM + d];
        float xv = x[lin];
        outq[lin] = q;
        float df = q - xv;
        sum = fmaf(df, df, sum);
    }
    red[tid] = sum;
    __syncthreads();
    #pragma unroll
    for (int o = 128; o; o >>= 1) { if (tid < o) red[tid] += red[tid + o]; __syncthreads(); }
    if (tid == 0) g_partials[blk] = red[0];
}

__global__ void counts_kernel(float* __restrict__ out_idx) {
    int n = blockIdx.x * 256 + threadIdx.x;
    int id = g_idx[n];
    atomicAdd(&g_counts[id], 1);
    out_idx[n] = (float)id;
}

__global__ void scatter_kernel(float* __restrict__ enc) {
    int n = blockIdx.x * 256 + threadIdx.x;
    enc[(size_t)n * KC + g_idx[n]] = 1.0f;
}

__global__ void finalize_kernel(float* __restrict__ out_loss, float* __restrict__ out_perp) {
    __shared__ float red[256];
    const int tid = threadIdx.x;

    float s = 0.f;
    for (int i = tid; i < 1024; i += 256) s += g_partials[i];
    red[tid] = s;
    __syncthreads();
    #pragma unroll
    for (int o = 128; o; o >>= 1) { if (tid < o) red[tid] += red[tid + o]; __syncthreads(); }
    if (tid == 0) {
        float mse = red[0] * (1.0f / 4194304.0f);
        float loss = mse * 1.25f;
        if (isnan(loss) || isinf(loss)) loss = 0.1f;
        *out_loss = loss;
    }
    __syncthreads();

    float hsum = 0.f;
    for (int i = tid; i < KC; i += 256) {
        float p = (float)g_counts[i] * (1.0f / (float)NTOT);
        hsum += p * logf(p + 1e-10f);
    }
    red[tid] = hsum;
    __syncthreads();
    #pragma unroll
    for (int o = 128; o; o >>= 1) { if (tid < o) red[tid] += red[tid + o]; __syncthreads(); }
    if (tid == 0) *out_perp = expf(-red[0]);
}

// ---------------- launch ----------------
extern "C" void kernel_launch(void* const* d_in, const int* in_sizes, int n_in,
                              void* d_out, int out_size) {
    const float* x;
    const float* w;
    if (in_sizes[0] == KC * DIM) { w = (const float*)d_in[0]; x = (const float*)d_in[1]; }
    else                         { x = (const float*)d_in[0]; w = (const float*)d_in[1]; }

    float* out = (float*)d_out;
    float* out_q    = out;
    float* out_loss = out + OFF_LOSS;
    float* out_perp = out + OFF_PERP;
    float* out_enc  = out + OFF_ENC;
    float* out_idx  = out + OFF_IDX;

    cudaFuncSetAttribute(argmin_mma_kernel, cudaFuncAttributeMaxDynamicSharedMemorySize, SMEM_TOTAL);

    prep_w_kernel<<<2048, 256>>>(w);
    wsq_kernel<<<512, 256>>>(w);
    zero_counts_kernel<<<16, 256>>>();
    argmin_mma_kernel<<<256, 256, SMEM_TOTAL>>>(x);
    rescue_kernel<<<128, 256>>>(x, w);
    gather_kernel<<<1024, 256>>>(x, w, out_q);
    counts_kernel<<<128, 256>>>(out_idx);
    cudaMemsetAsync(out_enc, 0, (size_t)134217728 * sizeof(float));
    scatter_kernel<<<128, 256>>>(out_enc);
    finalize_kernel<<<1, 256>>>(out_loss, out_perp);
}

// round 5
// speedup vs baseline: 1.6011x; 1.4311x over previous
#include <cuda_runtime.h>
#include <cuda_fp16.h>
#include <math.h>
#include <stdint.h>

#define NTOT 32768
#define DIM  128
#define KC   4096
#define CHW  131072

#define OFF_LOSS 4194304
#define OFF_PERP 4194305
#define OFF_ENC  4194306
#define OFF_IDX  138412034

#define GAP_THRESH 8e-4f

// ---------------- device scratch ----------------
__device__ __align__(16) __half g_Bp[KC * 256];   // [code][ w_hi(128) | w_lo(128) ], w scaled x64 (2MB)
__device__ float g_wsq[KC];
__device__ int   g_idx[NTOT];
__device__ int   g_counts[KC];
__device__ float g_partials[1024];
__device__ int   g_flag[NTOT];
__device__ int   g_nflag;

// ---------------- PTX helpers ----------------
__device__ __forceinline__ uint32_t smem_u32(const void* p) {
    uint32_t a;
    asm("{ .reg .u64 t; cvta.to.shared.u64 t, %1; cvt.u32.u64 %0, t; }" : "=r"(a) : "l"(p));
    return a;
}
__device__ __forceinline__ void cp_async16(uint32_t dst, const void* src) {
    asm volatile("cp.async.cg.shared.global [%0], [%1], 16;" :: "r"(dst), "l"(src) : "memory");
}
#define CP_COMMIT() asm volatile("cp.async.commit_group;" ::: "memory")
#define CP_WAIT1()  asm volatile("cp.async.wait_group 1;" ::: "memory")

#define LDSM4(R, addr) \
    asm volatile("ldmatrix.sync.aligned.m8n8.x4.shared.b16 {%0,%1,%2,%3}, [%4];" \
        : "=r"((R)[0]), "=r"((R)[1]), "=r"((R)[2]), "=r"((R)[3]) : "r"(addr))

#define MMA16816(C, A, b0, b1) \
    asm volatile("mma.sync.aligned.m16n8k16.row.col.f32.f16.f16.f32 " \
        "{%0,%1,%2,%3}, {%4,%5,%6,%7}, {%8,%9}, {%0,%1,%2,%3};" \
        : "+f"((C)[0]), "+f"((C)[1]), "+f"((C)[2]), "+f"((C)[3]) \
        : "r"((A)[0]), "r"((A)[1]), "r"((A)[2]), "r"((A)[3]), "r"(b0), "r"(b1))

// ---------------- prep: split scaled W into fp16 hi/lo pair rows ----------------
__global__ void prep_w_kernel(const float* __restrict__ w) {
    int i = blockIdx.x * 256 + threadIdx.x;     // 0..524287
    int k = i >> 7, d = i & 127;
    float v = w[i] * 64.0f;
    __half h = __float2half_rn(v);
    __half l = __float2half_rn(v - __half2float(h));
    g_Bp[k * 256 + d]       = h;
    g_Bp[k * 256 + 128 + d] = l;
}

__global__ void wsq_kernel(const float* __restrict__ w) {
    int warp = threadIdx.x >> 5, lane = threadIdx.x & 31;
    int k = blockIdx.x * 8 + warp;
    float4 v = ((const float4*)w)[k * 32 + lane];
    float s = v.x * v.x + v.y * v.y + v.z * v.z + v.w * v.w;
    #pragma unroll
    for (int o = 16; o; o >>= 1) s += __shfl_down_sync(0xffffffffu, s, o);
    if (lane == 0) g_wsq[k] = s;
}

__global__ void zero_counts_kernel() {
    g_counts[blockIdx.x * 256 + threadIdx.x] = 0;
    if (blockIdx.x == 0 && threadIdx.x == 0) g_nflag = 0;
}

// ---------------- fp16 split mma.sync distance GEMM + fused top-2 argmin ----------------
// CTA: 512 threads (2x8 warp grid), tile 128 rows x 256 codes/stage x K=256.
// A resident (pitch 264 halves = 528B); B 3-stage cp.async ring (stage = 256 codes x 64 halves).
#define A_PITCH 264
#define B_STG   36864
#define SM_A    0
#define SM_B    67584
#define SM_WSQ  178176
#define SM_XSQ  194560
#define SM_RV   195072
#define SM_RI   199168
#define SM_R2   203264
#define SMEM_TOTAL 207360

__global__ void __launch_bounds__(512, 1) argmin_mma_kernel(const float* __restrict__ x) {
    extern __shared__ char sm[];
    __half* Asm   = (__half*)(sm + SM_A);
    float*  wsq_s = (float*)(sm + SM_WSQ);
    float*  xsq_s = (float*)(sm + SM_XSQ);
    float*  rv    = (float*)(sm + SM_RV);
    int*    ri    = (int*)(sm + SM_RI);
    float*  r2    = (float*)(sm + SM_R2);
    const uint32_t smb = smem_u32(sm);

    const int tid   = threadIdx.x;
    const int lane  = tid & 31;
    const int warp  = tid >> 5;
    const int warpM = warp >> 3;      // 0..1
    const int warpN = warp & 7;       // 0..7
    const int n0 = blockIdx.x << 7;
    const int b  = n0 >> 10;
    const int nb = n0 & 1023;

    if (tid < 128) xsq_s[tid] = 0.f;
    __syncthreads();

    {
        float4* d4 = (float4*)wsq_s;
        const float4* s4 = (const float4*)g_wsq;
        #pragma unroll
        for (int i = tid; i < 1024; i += 512) d4[i] = s4[i];
    }

    // build A: [x_hi | x_hi], accumulate row sums of x^2 (full fp32 precision)
    const float* xb = x + (size_t)b * CHW + nb;
    for (int it = 0; it < 32; it++) {
        int e = it * 512 + tid;
        int d = e >> 7, r = e & 127;
        float v = __ldg(xb + (size_t)d * 1024 + r);
        __half h = __float2half_rn(v);
        Asm[r * A_PITCH + d]       = h;
        Asm[r * A_PITCH + 128 + d] = h;
        atomicAdd(&xsq_s[r], v * v);
    }
    __syncthreads();
    if (tid < 128) xsq_s[tid] += 1e-8f;
    __syncthreads();

    float xr[8];
    #pragma unroll
    for (int mt = 0; mt < 4; mt++) {
        int r0 = warpM * 64 + mt * 16 + (lane >> 2);
        xr[mt * 2]     = xsq_s[r0];
        xr[mt * 2 + 1] = xsq_s[r0 + 8];
    }

    const uint32_t a_base  = smb + SM_A +
        (uint32_t)((warpM * 64 + (lane & 15)) * 528 + ((lane >> 4) * 16));
    const uint32_t b_base0 = smb + SM_B +
        (uint32_t)((warpN * 32 + (lane & 7) + ((lane & 16) ? 8 : 0)) * 144 + ((lane & 8) ? 16 : 0));

    float acc[4][4][4];
    #pragma unroll
    for (int mt = 0; mt < 4; mt++)
        #pragma unroll
        for (int nt = 0; nt < 4; nt++)
            #pragma unroll
            for (int q = 0; q < 4; q++) acc[mt][nt][q] = 0.f;

    float bval[8]; int bidx[8]; float b2v[8];
    #pragma unroll
    for (int m = 0; m < 8; m++) { bval[m] = 3.4e38f; bidx[m] = 0; b2v[m] = 3.4e38f; }

    // cp.async stage issuer: stage s covers codes [(s>>2)*256, +256), k-halves [(s&3)*64, +64)
    const int brow = tid;   // 0..511 -> row = tid>>1, half = tid&1
    auto issue = [&](int st) {
        int stg = st % 3;
        int c = st >> 2, kq = st & 3;
        int row = brow >> 1, half = brow & 1;
        const char* src = (const char*)g_Bp + ((size_t)c * 256 + row) * 512 + kq * 128 + half * 64;
        uint32_t dst = smb + SM_B + stg * B_STG + row * 144 + half * 64;
        #pragma unroll
        for (int i = 0; i < 4; i++) cp_async16(dst + i * 16, src + i * 16);
    };

    issue(0); CP_COMMIT();
    issue(1); CP_COMMIT();

    for (int s = 0; s < 64; s++) {
        CP_WAIT1();
        __syncthreads();
        if (s + 2 < 64) issue(s + 2);
        CP_COMMIT();

        const int stg = s % 3;
        const int kq  = s & 3;
        const uint32_t abase = a_base + (uint32_t)(kq * 128);
        const uint32_t bbase = b_base0 + (uint32_t)(stg * B_STG);

        #pragma unroll
        for (int j = 0; j < 4; j++) {
            uint32_t ak = abase + j * 32;
            uint32_t bk = bbase + j * 32;
            uint32_t A0[4], A1[4], A2[4], A3[4], B0[4], B1[4];
            LDSM4(A0, ak);
            LDSM4(A1, ak + 16 * 528);
            LDSM4(A2, ak + 32 * 528);
            LDSM4(A3, ak + 48 * 528);
            LDSM4(B0, bk);
            LDSM4(B1, bk + 16 * 144);

            MMA16816(acc[0][0], A0, B0[0], B0[1]);
            MMA16816(acc[0][1], A0, B0[2], B0[3]);
            MMA16816(acc[0][2], A0, B1[0], B1[1]);
            MMA16816(acc[0][3], A0, B1[2], B1[3]);
            MMA16816(acc[1][0], A1, B0[0], B0[1]);
            MMA16816(acc[1][1], A1, B0[2], B0[3]);
            MMA16816(acc[1][2], A1, B1[0], B1[1]);
            MMA16816(acc[1][3], A1, B1[2], B1[3]);
            MMA16816(acc[2][0], A2, B0[0], B0[1]);
            MMA16816(acc[2][1], A2, B0[2], B0[3]);
            MMA16816(acc[2][2], A2, B1[0], B1[1]);
            MMA16816(acc[2][3], A2, B1[2], B1[3]);
            MMA16816(acc[3][0], A3, B0[0], B0[1]);
            MMA16816(acc[3][1], A3, B0[2], B0[3]);
            MMA16816(acc[3][2], A3, B1[0], B1[1]);
            MMA16816(acc[3][3], A3, B1[2], B1[3]);
        }

        if (kq == 3) {
            const int cb = (s >> 2) * 256 + warpN * 32 + (lane & 3) * 2;
            #pragma unroll
            for (int nt = 0; nt < 4; nt++) {
                int c0 = cb + nt * 8;
                float w0 = wsq_s[c0], w1 = wsq_s[c0 + 1];
                #pragma unroll
                for (int mt = 0; mt < 4; mt++) {
                    float* a4 = acc[mt][nt];
                    float d00 = fmaf(a4[0], -0.03125f, xr[mt * 2])     + w0;
                    float d01 = fmaf(a4[1], -0.03125f, xr[mt * 2])     + w1;
                    float d10 = fmaf(a4[2], -0.03125f, xr[mt * 2 + 1]) + w0;
                    float d11 = fmaf(a4[3], -0.03125f, xr[mt * 2 + 1]) + w1;
                    int m0 = mt * 2, m1 = mt * 2 + 1;
                    if (d00 < bval[m0]) { b2v[m0] = bval[m0]; bval[m0] = d00; bidx[m0] = c0; }
                    else if (d00 < b2v[m0]) b2v[m0] = d00;
                    if (d01 < bval[m0]) { b2v[m0] = bval[m0]; bval[m0] = d01; bidx[m0] = c0 + 1; }
                    else if (d01 < b2v[m0]) b2v[m0] = d01;
                    if (d10 < bval[m1]) { b2v[m1] = bval[m1]; bval[m1] = d10; bidx[m1] = c0; }
                    else if (d10 < b2v[m1]) b2v[m1] = d10;
                    if (d11 < bval[m1]) { b2v[m1] = bval[m1]; bval[m1] = d11; bidx[m1] = c0 + 1; }
                    else if (d11 < b2v[m1]) b2v[m1] = d11;
                    a4[0] = 0.f; a4[1] = 0.f; a4[2] = 0.f; a4[3] = 0.f;
                }
            }
        }
    }

    // top-2 merge across the 4 lanes sharing each row
    #pragma unroll
    for (int m = 0; m < 8; m++) {
        #pragma unroll
        for (int off = 1; off < 4; off <<= 1) {
            float ov = __shfl_xor_sync(0xffffffffu, bval[m], off);
            int   oi = __shfl_xor_sync(0xffffffffu, bidx[m], off);
            float os = __shfl_xor_sync(0xffffffffu, b2v[m], off);
            if (ov < bval[m] || (ov == bval[m] && oi < bidx[m])) {
                b2v[m] = fminf(bval[m], os);
                bval[m] = ov; bidx[m] = oi;
            } else {
                b2v[m] = fminf(b2v[m], ov);
            }
        }
    }
    if ((lane & 3) == 0) {
        #pragma unroll
        for (int mt = 0; mt < 4; mt++) {
            int r0 = warpM * 64 + mt * 16 + (lane >> 2);
            rv[warpN * 128 + r0]     = bval[mt * 2];
            ri[warpN * 128 + r0]     = bidx[mt * 2];
            r2[warpN * 128 + r0]     = b2v[mt * 2];
            rv[warpN * 128 + r0 + 8] = bval[mt * 2 + 1];
            ri[warpN * 128 + r0 + 8] = bidx[mt * 2 + 1];
            r2[warpN * 128 + r0 + 8] = b2v[mt * 2 + 1];
        }
    }
    __syncthreads();
    if (tid < 128) {
        float bv = rv[tid]; int bi = ri[tid]; float s2 = r2[tid];
        #pragma unroll
        for (int q = 1; q < 8; q++) {
            float v = rv[q * 128 + tid]; int ii = ri[q * 128 + tid]; float os = r2[q * 128 + tid];
            if (v < bv || (v == bv && ii < bi)) { s2 = fminf(bv, os); bv = v; bi = ii; }
            else                                { s2 = fminf(s2, v); }
        }
        g_idx[n0 + tid] = bi;
        if (s2 - bv < GAP_THRESH) {
            int p = atomicAdd(&g_nflag, 1);
            g_flag[p] = n0 + tid;
        }
    }
}

// ---------------- rescue: exact fp32 re-argmin for near-tie rows ----------------
__global__ void __launch_bounds__(256, 1) rescue_kernel(const float* __restrict__ x,
                                                        const float* __restrict__ w) {
    __shared__ __align__(16) float xs[4][128];
    __shared__ float xsq_sh[4];
    __shared__ float redv[256];
    __shared__ int   redi[256];
    const int tid = threadIdx.x;
    const int nf = g_nflag;

    for (int base = blockIdx.x * 4; base < nf; base += gridDim.x * 4) {
        const int cnt = min(4, nf - base);
        __syncthreads();
        if (tid < 128) {
            for (int r = 0; r < cnt; r++) {
                int row = g_flag[base + r];
                int bb = row >> 10, nb = row & 1023;
                xs[r][tid] = x[(size_t)bb * CHW + (size_t)tid * 1024 + nb];
            }
        }
        __syncthreads();
        if (tid < 4) {
            float s = 0.f;
            if (tid < cnt)
                for (int d = 0; d < 128; d++) s = fmaf(xs[tid][d], xs[tid][d], s);
            xsq_sh[tid] = s + 1e-8f;
        }
        __syncthreads();

        float bv[4]; int bi[4];
        #pragma unroll
        for (int r = 0; r < 4; r++) { bv[r] = 3.4e38f; bi[r] = 0; }

        const float4* w4 = (const float4*)w;
        for (int g = 0; g < 4; g++) {
            const int k0 = g * 1024 + tid * 4;
            float dacc[4][4];
            #pragma unroll
            for (int r = 0; r < 4; r++)
                #pragma unroll
                for (int j = 0; j < 4; j++) dacc[r][j] = 0.f;
            #pragma unroll 4
            for (int d4 = 0; d4 < 32; d4++) {
                float4 xv[4];
                #pragma unroll
                for (int r = 0; r < 4; r++) xv[r] = ((const float4*)xs[r])[d4];
                #pragma unroll
                for (int j = 0; j < 4; j++) {
                    float4 wv = w4[(size_t)(k0 + j) * 32 + d4];
                    #pragma unroll
                    for (int r = 0; r < 4; r++) {
                        float t = dacc[r][j];
                        t = fmaf(xv[r].x, wv.x, t);
                        t = fmaf(xv[r].y, wv.y, t);
                        t = fmaf(xv[r].z, wv.z, t);
                        t = fmaf(xv[r].w, wv.w, t);
                        dacc[r][j] = t;
                    }
                }
            }
            #pragma unroll
            for (int j = 0; j < 4; j++) {
                int k = k0 + j;
                float wq = g_wsq[k];
                #pragma unroll
                for (int r = 0; r < 4; r++) {
                    float dist = fmaf(-2.f, dacc[r][j], xsq_sh[r]) + wq;
                    if (dist < bv[r]) { bv[r] = dist; bi[r] = k; }
                }
            }
        }

        for (int r = 0; r < cnt; r++) {
            redv[tid] = bv[r]; redi[tid] = bi[r];
            __syncthreads();
            for (int o = 128; o; o >>= 1) {
                if (tid < o) {
                    float v = redv[tid + o]; int ii = redi[tid + o];
                    if (v < redv[tid] || (v == redv[tid] && ii < redi[tid])) { redv[tid] = v; redi[tid] = ii; }
                }
                __syncthreads();
            }
            if (tid == 0) g_idx[g_flag[base + r]] = redi[0];
            __syncthreads();
        }
    }
}

// ---------------- gather quantized + loss partials ----------------
__global__ void gather_kernel(const float* __restrict__ x, const float* __restrict__ wgt,
                              float* __restrict__ outq) {
    __shared__ int idx_s[32];
    __shared__ float red[256];
    const int blk = blockIdx.x;
    const int b = blk >> 5, h = blk & 31;
    const int n0 = blk * 32;
    const int tid = threadIdx.x;
    if (tid < 32) idx_s[tid] = g_idx[n0 + tid];
    __syncthreads();

    const int w = tid & 31, dg = tid >> 5;
    const size_t bse = (size_t)b * CHW + h * 32 + w;
    float sum = 0.f;
    #pragma unroll
    for (int j = 0; j < 16; j++) {
        int d = dg + (j << 3);
        size_t lin = bse + (size_t)d * 1024;
        float q = wgt[idx_s[w] * DIM + d];
        float xv = x[lin];
        outq[lin] = q;
        float df = q - xv;
        sum = fmaf(df, df, sum);
    }
    red[tid] = sum;
    __syncthreads();
    #pragma unroll
    for (int o = 128; o; o >>= 1) { if (tid < o) red[tid] += red[tid + o]; __syncthreads(); }
    if (tid == 0) g_partials[blk] = red[0];
}

__global__ void counts_kernel(float* __restrict__ out_idx) {
    int n = blockIdx.x * 256 + threadIdx.x;
    int id = g_idx[n];
    atomicAdd(&g_counts[id], 1);
    out_idx[n] = (float)id;
}

__global__ void scatter_kernel(float* __restrict__ enc) {
    int n = blockIdx.x * 256 + threadIdx.x;
    enc[(size_t)n * KC + g_idx[n]] = 1.0f;
}

__global__ void finalize_kernel(float* __restrict__ out_loss, float* __restrict__ out_perp) {
    __shared__ float red[256];
    const int tid = threadIdx.x;

    float s = 0.f;
    for (int i = tid; i < 1024; i += 256) s += g_partials[i];
    red[tid] = s;
    __syncthreads();
    #pragma unroll
    for (int o = 128; o; o >>= 1) { if (tid < o) red[tid] += red[tid + o]; __syncthreads(); }
    if (tid == 0) {
        float mse = red[0] * (1.0f / 4194304.0f);
        float loss = mse * 1.25f;
        if (isnan(loss) || isinf(loss)) loss = 0.1f;
        *out_loss = loss;
    }
    __syncthreads();

    float hsum = 0.f;
    for (int i = tid; i < KC; i += 256) {
        float p = (float)g_counts[i] * (1.0f / (float)NTOT);
        hsum += p * logf(p + 1e-10f);
    }
    red[tid] = hsum;
    __syncthreads();
    #pragma unroll
    for (int o = 128; o; o >>= 1) { if (tid < o) red[tid] += red[tid + o]; __syncthreads(); }
    if (tid == 0) *out_perp = expf(-red[0]);
}

// ---------------- launch ----------------
extern "C" void kernel_launch(void* const* d_in, const int* in_sizes, int n_in,
                              void* d_out, int out_size) {
    const float* x;
    const float* w;
    if (in_sizes[0] == KC * DIM) { w = (const float*)d_in[0]; x = (const float*)d_in[1]; }
    else                         { x = (const float*)d_in[0]; w = (const float*)d_in[1]; }

    float* out = (float*)d_out;
    float* out_q    = out;
    float* out_loss = out + OFF_LOSS;
    float* out_perp = out + OFF_PERP;
    float* out_enc  = out + OFF_ENC;
    float* out_idx  = out + OFF_IDX;

    cudaFuncSetAttribute(argmin_mma_kernel, cudaFuncAttributeMaxDynamicSharedMemorySize, SMEM_TOTAL);

    prep_w_kernel<<<2048, 256>>>(w);
    wsq_kernel<<<512, 256>>>(w);
    zero_counts_kernel<<<16, 256>>>();
    argmin_mma_kernel<<<256, 512, SMEM_TOTAL>>>(x);
    rescue_kernel<<<128, 256>>>(x, w);
    gather_kernel<<<1024, 256>>>(x, w, out_q);
    counts_kernel<<<128, 256>>>(out_idx);
    cudaMemsetAsync(out_enc, 0, (size_t)134217728 * sizeof(float));
    scatter_kernel<<<128, 256>>>(out_enc);
    finalize_kernel<<<1, 256>>>(out_loss, out_perp);
}